// round 10
// baseline (speedup 1.0000x reference)
#include <cuda_runtime.h>
#include <cuda_fp16.h>
#include <cstdint>

// Problem constants
#define N_ROWS 16384
#define KNB    25
#define DIM    512
#define ODIM   1024

// GEMM tiling (R5/R9 baseline)
#define BM 128
#define BN 128
#define BK 32
#define SROW 40
#define STAGES 3
#define NKT (DIM / BK)

#define TILE_HALVES (BM * SROW)
#define SMEM_BYTES  (STAGES * 2 * TILE_HALVES * 2)   // 61440

// Pipeline split
#define QROWS (N_ROWS / 4)            // 4096 rows per quarter
#define MEAN_CTAS_Q (QROWS / 2)       // 2048 (2 rows per CTA)
#define GEMM_MB_Q (QROWS / BM)        // 32
#define GEMM_NB (ODIM / BN)           // 8
#define GEMM_CTAS_Q (GEMM_MB_Q * GEMM_NB)   // 256
#define MIXED_CTAS (MEAN_CTAS_Q + GEMM_CTAS_Q) // 2304 = 256*9

// Scratch (device globals)
__device__ __half g_A [N_ROWS * DIM];
__device__ __half g_WT[ODIM  * DIM];

// ---------------------------------------------------------------------------
// helpers
// ---------------------------------------------------------------------------
__device__ __forceinline__ uint32_t smem_addr32(const void* p) {
    return (uint32_t)__cvta_generic_to_shared(p);
}
__device__ __forceinline__ void ldmatrix_x4(uint32_t& r0, uint32_t& r1,
                                            uint32_t& r2, uint32_t& r3, uint32_t addr) {
    asm volatile("ldmatrix.sync.aligned.m8n8.x4.shared.b16 {%0,%1,%2,%3}, [%4];"
                 : "=r"(r0), "=r"(r1), "=r"(r2), "=r"(r3) : "r"(addr));
}
__device__ __forceinline__ void mma16816(float* c, const uint32_t* a, const uint32_t* b) {
    asm volatile(
        "mma.sync.aligned.m16n8k16.row.col.f32.f16.f16.f32 "
        "{%0,%1,%2,%3}, {%4,%5,%6,%7}, {%8,%9}, {%0,%1,%2,%3};"
        : "+f"(c[0]), "+f"(c[1]), "+f"(c[2]), "+f"(c[3])
        : "r"(a[0]), "r"(a[1]), "r"(a[2]), "r"(a[3]), "r"(b[0]), "r"(b[1]));
}
__device__ __forceinline__ void cp_async16(uint32_t dst, const void* src) {
    asm volatile("cp.async.cg.shared.global [%0], [%1], 16;" :: "r"(dst), "l"(src));
}

// ---------------------------------------------------------------------------
// Kernel 1: W transpose -> fp16 [O, D]
// ---------------------------------------------------------------------------
__global__ void __launch_bounds__(256) wprep_kernel(const float* __restrict__ W)
{
    __shared__ __half s[64 * 65];
    int bk = blockIdx.x & 7;
    int bo = blockIdx.x >> 3;
    int tid = threadIdx.x;

    #pragma unroll
    for (int i = 0; i < 16; i++) {
        int idx = tid + i * 256;
        int kk = idx >> 6, oo = idx & 63;
        s[kk * 65 + oo] = __float2half_rn(W[(size_t)(bk * 64 + kk) * ODIM + bo * 64 + oo]);
    }
    __syncthreads();
    #pragma unroll
    for (int i = 0; i < 16; i++) {
        int idx = tid + i * 256;
        int oo = idx >> 6, kk = idx & 63;
        g_WT[(size_t)(bo * 64 + oo) * DIM + bk * 64 + kk] = s[kk * 65 + oo];
    }
}

// ---------------------------------------------------------------------------
// Mean body: 2 rows per 256-thread CTA, front-batched MLP-25, __ldcs
// ---------------------------------------------------------------------------
__device__ __forceinline__ void do_mean2(int row_base, const float* __restrict__ self_vecs,
                                         const float* __restrict__ neigh, int tid)
{
    int r = row_base + (tid >> 7);
    int t = tid & 127;

    const float4* nv = (const float4*)neigh + (size_t)r * KNB * (DIM / 4) + t;
    float4 acc = __ldg((const float4*)self_vecs + (size_t)r * (DIM / 4) + t);

    float4 v[KNB];
    #pragma unroll
    for (int k = 0; k < KNB; k++)
        v[k] = __ldcs(nv + (size_t)k * (DIM / 4));

    #pragma unroll
    for (int k = 0; k < KNB; k++) {
        acc.x += v[k].x; acc.y += v[k].y; acc.z += v[k].z; acc.w += v[k].w;
    }
    const float inv = 1.0f / (float)(KNB + 1);
    acc.x *= inv; acc.y *= inv; acc.z *= inv; acc.w *= inv;

    __half2* out = (__half2*)g_A + (size_t)r * (DIM / 2);
    out[t * 2 + 0] = __floats2half2_rn(acc.x, acc.y);
    out[t * 2 + 1] = __floats2half2_rn(acc.z, acc.w);
}

// ---------------------------------------------------------------------------
// GEMM body: 128x128 tile, 3-stage cp.async ring (R5), bias+relu epilogue
// ---------------------------------------------------------------------------
__device__ __forceinline__ void do_gemm_tile(int mb, int nb, const float* __restrict__ bias,
                                             float* __restrict__ out, __half* smem_dyn, int tid)
{
    int wid = tid >> 5;
    int lane = tid & 31;
    int warp_m = wid & 3;
    int warp_n = wid >> 2;
    int m0 = mb * BM;
    int n0 = nb * BN;

    const __half* gA = g_A  + (size_t)m0 * DIM;
    const __half* gB = g_WT + (size_t)n0 * DIM;

    float acc[2][8][4];
    #pragma unroll
    for (int i = 0; i < 2; i++)
        #pragma unroll
        for (int j = 0; j < 8; j++)
            #pragma unroll
            for (int v = 0; v < 4; v++) acc[i][j][v] = 0.0f;

    uint32_t sA_base[STAGES], sB_base[STAGES];
    uint32_t sdyn = smem_addr32(smem_dyn);
    #pragma unroll
    for (int s = 0; s < STAGES; s++) {
        sA_base[s] = sdyn + (uint32_t)(s * TILE_HALVES) * 2u;
        sB_base[s] = sdyn + (uint32_t)((STAGES + s) * TILE_HALVES) * 2u;
    }

    int cp_row = tid >> 2;
    int cp_c   = (tid & 3) * 8;
    int cp_row2 = (tid + 256) >> 2;
    int cp_c2   = ((tid + 256) & 3) * 8;

    int a_row = warp_m * 32 + (lane & 15);
    int a_colb = ((lane >> 4) << 3);
    int quad = lane >> 3;
    int b_row_off = ((quad >> 1) << 3) + (lane & 7);
    int b_colb = ((quad & 1) << 3);

    #pragma unroll
    for (int p = 0; p < 2; p++) {
        int kb = p * BK;
        cp_async16(sA_base[p] + (cp_row  * SROW + cp_c ) * 2, gA + (size_t)cp_row  * DIM + kb + cp_c );
        cp_async16(sA_base[p] + (cp_row2 * SROW + cp_c2) * 2, gA + (size_t)cp_row2 * DIM + kb + cp_c2);
        cp_async16(sB_base[p] + (cp_row  * SROW + cp_c ) * 2, gB + (size_t)cp_row  * DIM + kb + cp_c );
        cp_async16(sB_base[p] + (cp_row2 * SROW + cp_c2) * 2, gB + (size_t)cp_row2 * DIM + kb + cp_c2);
        asm volatile("cp.async.commit_group;");
    }

    #pragma unroll 4
    for (int kt = 0; kt < NKT; kt++) {
        asm volatile("cp.async.wait_group 1;");
        __syncthreads();

        if (kt + 2 < NKT) {
            int buf = (kt + 2) % STAGES;
            int kb = (kt + 2) * BK;
            cp_async16(sA_base[buf] + (cp_row  * SROW + cp_c ) * 2, gA + (size_t)cp_row  * DIM + kb + cp_c );
            cp_async16(sA_base[buf] + (cp_row2 * SROW + cp_c2) * 2, gA + (size_t)cp_row2 * DIM + kb + cp_c2);
            cp_async16(sB_base[buf] + (cp_row  * SROW + cp_c ) * 2, gB + (size_t)cp_row  * DIM + kb + cp_c );
            cp_async16(sB_base[buf] + (cp_row2 * SROW + cp_c2) * 2, gB + (size_t)cp_row2 * DIM + kb + cp_c2);
        }
        asm volatile("cp.async.commit_group;");

        int buf = kt % STAGES;
        #pragma unroll
        for (int ks = 0; ks < 2; ks++) {
            uint32_t af[2][4];
            #pragma unroll
            for (int mt = 0; mt < 2; mt++) {
                uint32_t addr = sA_base[buf] +
                    ((a_row + mt * 16) * SROW + ks * 16 + a_colb) * 2;
                ldmatrix_x4(af[mt][0], af[mt][1], af[mt][2], af[mt][3], addr);
            }
            uint32_t bf[8][2];
            #pragma unroll
            for (int ntp = 0; ntp < 4; ntp++) {
                uint32_t r0, r1, r2, r3;
                uint32_t addr = sB_base[buf] +
                    ((warp_n * 64 + ntp * 16 + b_row_off) * SROW + ks * 16 + b_colb) * 2;
                ldmatrix_x4(r0, r1, r2, r3, addr);
                bf[ntp * 2 + 0][0] = r0; bf[ntp * 2 + 0][1] = r1;
                bf[ntp * 2 + 1][0] = r2; bf[ntp * 2 + 1][1] = r3;
            }
            #pragma unroll
            for (int mt = 0; mt < 2; mt++)
                #pragma unroll
                for (int nt = 0; nt < 8; nt++)
                    mma16816(acc[mt][nt], af[mt], bf[nt]);
        }
    }

    #pragma unroll
    for (int nt = 0; nt < 8; nt++) {
        int col = n0 + warp_n * 64 + nt * 8 + ((lane & 3) << 1);
        float b0 = bias[col], b1 = bias[col + 1];
        #pragma unroll
        for (int mt = 0; mt < 2; mt++) {
            int row = m0 + warp_m * 32 + mt * 16 + (lane >> 2);
            float2 v0, v1;
            v0.x = fmaxf(acc[mt][nt][0] + b0, 0.0f);
            v0.y = fmaxf(acc[mt][nt][1] + b1, 0.0f);
            v1.x = fmaxf(acc[mt][nt][2] + b0, 0.0f);
            v1.y = fmaxf(acc[mt][nt][3] + b1, 0.0f);
            *(float2*)(out + (size_t)row * ODIM + col) = v0;
            *(float2*)(out + (size_t)(row + 8) * ODIM + col) = v1;
        }
    }
}

// ---------------------------------------------------------------------------
// Standalone kernels
// ---------------------------------------------------------------------------
__global__ void __launch_bounds__(256, 2) mean_kernel(const float* __restrict__ self_vecs,
                                                      const float* __restrict__ neigh,
                                                      int row_ofs)
{
    do_mean2(row_ofs + blockIdx.x * 2, self_vecs, neigh, threadIdx.x);
}

__global__ void __launch_bounds__(256, 2) gemm_kernel(const float* __restrict__ bias,
                                                      float* __restrict__ out, int mb_ofs)
{
    extern __shared__ __half smem_dyn[];
    do_gemm_tile(mb_ofs + blockIdx.x, blockIdx.y, bias, out, smem_dyn, threadIdx.x);
}

// ---------------------------------------------------------------------------
// Mixed kernel: static role split — 8 of 9 CTAs do mean (quarter qm),
// 1 of 9 does a gemm tile (quarter qg). No atomics/flags: cross-launch
// ordering guarantees gemm inputs are ready.
// ---------------------------------------------------------------------------
__global__ void __launch_bounds__(256, 2) mixed_kernel(
    const float* __restrict__ self_vecs, const float* __restrict__ neigh,
    const float* __restrict__ bias, float* __restrict__ out,
    int qm_row_ofs, int qg_mb_ofs)
{
    extern __shared__ __half smem_dyn[];
    int bid = blockIdx.x;
    int r9 = bid % 9;
    int q9 = bid / 9;
    if (r9 == 8) {
        // gemm tile: q9 in [0, 256) -> mb = q9>>3, nb = q9&7
        do_gemm_tile(qg_mb_ofs + (q9 >> 3), q9 & 7, bias, out, smem_dyn, threadIdx.x);
    } else {
        // mean: idx = q9*8 + r9 in [0, 2048) -> 2 rows each
        do_mean2(qm_row_ofs + (q9 * 8 + r9) * 2, self_vecs, neigh, threadIdx.x);
    }
}

// ---------------------------------------------------------------------------
// Launch: 4-quarter software pipeline
// ---------------------------------------------------------------------------
extern "C" void kernel_launch(void* const* d_in, const int* in_sizes, int n_in,
                              void* d_out, int out_size)
{
    const float* self_vecs = (const float*)d_in[0];
    const float* neigh     = (const float*)d_in[1];
    const float* W         = (const float*)d_in[3];
    const float* b         = (const float*)d_in[4];
    float* out = (float*)d_out;

    static bool attr_set = false;
    if (!attr_set) {
        cudaFuncSetAttribute(gemm_kernel,  cudaFuncAttributeMaxDynamicSharedMemorySize, SMEM_BYTES);
        cudaFuncSetAttribute(mixed_kernel, cudaFuncAttributeMaxDynamicSharedMemorySize, SMEM_BYTES);
        attr_set = true;
    }

    wprep_kernel<<<128, 256>>>(W);
    mean_kernel<<<MEAN_CTAS_Q, 256>>>(self_vecs, neigh, 0);                       // mean Q0
    mixed_kernel<<<MIXED_CTAS, 256, SMEM_BYTES>>>(self_vecs, neigh, b, out,
                                                  1 * QROWS, 0 * GEMM_MB_Q);      // mean Q1 | gemm Q0
    mixed_kernel<<<MIXED_CTAS, 256, SMEM_BYTES>>>(self_vecs, neigh, b, out,
                                                  2 * QROWS, 1 * GEMM_MB_Q);      // mean Q2 | gemm Q1
    mixed_kernel<<<MIXED_CTAS, 256, SMEM_BYTES>>>(self_vecs, neigh, b, out,
                                                  3 * QROWS, 2 * GEMM_MB_Q);      // mean Q3 | gemm Q2
    dim3 gg(GEMM_MB_Q, GEMM_NB);
    gemm_kernel<<<gg, 256, SMEM_BYTES>>>(b, out, 3 * GEMM_MB_Q);                  // gemm Q3
}